// round 14
// baseline (speedup 1.0000x reference)
#include <cuda_runtime.h>
#include <math.h>

#define NBINS    16384
#define DIM      1024
#define MULT     128
#define ROWLEN   (DIM * MULT)   // 131072 elements per batch row
#define NROWS    128
#define NCTAS    (NROWS * 2)
#define NTHR     512

// ---------------------------------------------------------------------------
// XLA:CPU vectorized expf (GenerateVF32Exp, Cephes) — verified bit-compatible
// with the reference in R9. DO NOT TOUCH.
// ---------------------------------------------------------------------------
__device__ __forceinline__ float exp_ref(float xin) {
    float x = fminf(xin, 88.3762626647950f);
    x = fmaxf(x, -88.3762626647949f);
    float fx = floorf(__fmaf_rn(x, 1.44269504088896341f, 0.5f));
    x = __fmaf_rn(fx, -0.693359375f, x);
    x = __fmaf_rn(fx,  2.12194440e-4f, x);
    float z2 = __fmul_rn(x, x);
    float y = __fmaf_rn(1.9875691500E-4f, x, 1.3981999507E-3f);
    y = __fmaf_rn(y, x, 8.3334519073E-3f);
    y = __fmaf_rn(y, x, 4.1665795894E-2f);
    y = __fmaf_rn(y, x, 1.6666665459E-1f);
    y = __fmaf_rn(y, x, 5.0000001201E-1f);
    y = __fmaf_rn(y, z2, x);
    y = __fadd_rn(y, 1.0f);
    int n = (int)fx;
    float scale = __int_as_float((n + 127) << 23);
    float r = __fmul_rn(y, scale);
    return fmaxf(r, xin);
}

// Scratch (static device globals — no allocation)
__device__ float2   g_mm[NCTAS];            // per-CTA half-row min/max
__device__ int      g_ph[NCTAS * NBINS];    // per-CTA partial histogram
__device__ unsigned g_bar1[NROWS];          // monotone ticket counters
__device__ unsigned g_bar2[NROWS];          // (replay-safe, never reset)

// Row-pair barrier: publish (threadfence) + ticket arrive + spin.
// Counter is monotone; each launch adds exactly 2 per row, so
// target = (old & ~1) + 2 is correct for every graph replay.
__device__ __forceinline__ void row_barrier(unsigned* ctr) {
    __threadfence();          // publish this thread's prior global stores
    __syncthreads();          // all threads' stores+fences done
    if (threadIdx.x == 0) {
        unsigned old = atomicAdd(ctr, 1u);
        unsigned target = (old & ~1u) + 2u;
        while (*(volatile unsigned*)ctr < target) { }
        __threadfence();
    }
    __syncthreads();
}

// Dynamic shared: the 16384-bin histogram (64 KB)
extern __shared__ int sh_hist[];

__global__ void __launch_bounds__(NTHR, 2)
pd_kernel(const float* __restrict__ z_mean, const float* __restrict__ z_var,
          const float* __restrict__ x, const float* __restrict__ eps,
          float* __restrict__ out)
{
    __shared__ float s_ra[16], s_rb[16];
    __shared__ float s_sum;
    __shared__ int   s_ri[16], s_cmax;

    const int cta  = blockIdx.x;
    const int row  = cta >> 1;
    const int half = cta & 1;
    const int t    = threadIdx.x;     // 0..511
    const int lane = t & 31;
    const int warp = t >> 5;
    const int d4   = t & 255;          // float4 column of the dim axis
    const int rh   = t >> 8;           // 0/1: repeat-row parity in this half

    // zero the histogram up front — overlaps pass A's load stream
    #pragma unroll
    for (int i = t; i < NBINS; i += NTHR) sh_hist[i] = 0;

    const float4* e4 = reinterpret_cast<const float4*>(eps + (size_t)row * ROWLEN);
    const int rbeg = half * 64 + rh;   // this CTA covers repeat-rows [half*64, half*64+64)
    const int rend = half * 64 + 64;

    // ---------------- Pass A: eps min/max over this half ----------------
    // Monotonicity: sg>0, IEEE rounding monotone => row z-extremes are z at
    // the per-column eps extremes. Bitwise identical to full reduction.
    float4 emin = make_float4(INFINITY, INFINITY, INFINITY, INFINITY);
    float4 emax = make_float4(-INFINITY, -INFINITY, -INFINITY, -INFINITY);
    #pragma unroll 8
    for (int r = rbeg; r < rend; r += 2) {
        float4 e = e4[r * 256 + d4];
        emin.x = fminf(emin.x, e.x); emax.x = fmaxf(emax.x, e.x);
        emin.y = fminf(emin.y, e.y); emax.y = fmaxf(emax.y, e.y);
        emin.z = fminf(emin.z, e.z); emax.z = fmaxf(emax.z, e.z);
        emin.w = fminf(emin.w, e.w); emax.w = fmaxf(emax.w, e.w);
    }

    const float4 m4 = reinterpret_cast<const float4*>(z_mean + (size_t)row * DIM)[d4];
    const float4 v4 = reinterpret_cast<const float4*>(z_var  + (size_t)row * DIM)[d4];
    float4 sg;
    sg.x = exp_ref(__fmul_rn(0.5f, v4.x));
    sg.y = exp_ref(__fmul_rn(0.5f, v4.y));
    sg.z = exp_ref(__fmul_rn(0.5f, v4.z));
    sg.w = exp_ref(__fmul_rn(0.5f, v4.w));

    // z at the eps extremes (separate mul+add, as the reference)
    float vmin = fminf(
        fminf(__fadd_rn(m4.x, __fmul_rn(sg.x, emin.x)),
              __fadd_rn(m4.y, __fmul_rn(sg.y, emin.y))),
        fminf(__fadd_rn(m4.z, __fmul_rn(sg.z, emin.z)),
              __fadd_rn(m4.w, __fmul_rn(sg.w, emin.w))));
    float vmax = fmaxf(
        fmaxf(__fadd_rn(m4.x, __fmul_rn(sg.x, emax.x)),
              __fadd_rn(m4.y, __fmul_rn(sg.y, emax.y))),
        fmaxf(__fadd_rn(m4.z, __fmul_rn(sg.z, emax.z)),
              __fadd_rn(m4.w, __fmul_rn(sg.w, emax.w))));

    #pragma unroll
    for (int o = 16; o; o >>= 1) {
        vmin = fminf(vmin, __shfl_xor_sync(0xffffffffu, vmin, o));
        vmax = fmaxf(vmax, __shfl_xor_sync(0xffffffffu, vmax, o));
    }
    if (lane == 0) { s_ra[warp] = vmin; s_rb[warp] = vmax; }
    __syncthreads();
    if (t == 0) {
        float a = s_ra[0], m = s_rb[0];
        #pragma unroll
        for (int w = 1; w < 16; w++) { a = fminf(a, s_ra[w]); m = fmaxf(m, s_rb[w]); }
        g_mm[cta] = make_float2(a, m);      // own slot, plain store
    }

    row_barrier(&g_bar1[row]);

    // combine with partner (min/max order-free => bitwise identical)
    float2 mm0 = g_mm[row * 2];
    float2 mm1 = g_mm[row * 2 + 1];
    const float mn    = fminf(mm0.x, mm1.x);
    const float recip = __fdiv_rn(1.0f, __fsub_rn(fmaxf(mm0.y, mm1.y), mn));

    // ---------------- Pass B: partial histogram (verified numerics) --------
    #pragma unroll 4
    for (int r = rbeg; r < rend; r += 2) {
        float4 e = e4[r * 256 + d4];
        float zz[4];
        zz[0] = __fadd_rn(m4.x, __fmul_rn(sg.x, e.x));
        zz[1] = __fadd_rn(m4.y, __fmul_rn(sg.y, e.y));
        zz[2] = __fadd_rn(m4.z, __fmul_rn(sg.z, e.z));
        zz[3] = __fadd_rn(m4.w, __fmul_rn(sg.w, e.w));
        #pragma unroll
        for (int j = 0; j < 4; j++) {
            float s  = __fmul_rn(__fsub_rn(zz[j], mn), recip);
            float a  = __fmul_rn(s, 16384.0f);
            int   ia = (int)a;               // a >= 0 always (z >= mn)
            ia = ia > NBINS - 1 ? NBINS - 1 : ia;
            atomicAdd(&sh_hist[ia], 1);
        }
    }
    __syncthreads();

    // dump partial hist (coalesced int4), then row barrier
    {
        int4* dst = reinterpret_cast<int4*>(g_ph + (size_t)cta * NBINS);
        const int4* src = reinterpret_cast<const int4*>(sh_hist);
        #pragma unroll
        for (int k = 0; k < 8; k++) dst[t + k * NTHR] = src[t + k * NTHR];
    }

    row_barrier(&g_bar2[row]);

    // merge the two partials (integer, exact) and find cmax
    const int4* pa = reinterpret_cast<const int4*>(g_ph + (size_t)(row * 2) * NBINS);
    const int4* pb = reinterpret_cast<const int4*>(g_ph + (size_t)(row * 2 + 1) * NBINS);
    int4* shm4 = reinterpret_cast<int4*>(sh_hist);
    int cmax = 0;
    #pragma unroll
    for (int k = 0; k < 8; k++) {
        int i = t + k * NTHR;
        int4 a = pa[i], bq = pb[i];
        int4 c = make_int4(a.x + bq.x, a.y + bq.y, a.z + bq.z, a.w + bq.w);
        shm4[i] = c;
        cmax = max(cmax, max(max(c.x, c.y), max(c.z, c.w)));
    }
    #pragma unroll
    for (int o = 16; o; o >>= 1) cmax = max(cmax, __shfl_xor_sync(0xffffffffu, cmax, o));
    if (lane == 0) s_ri[warp] = cmax;
    __syncthreads();
    if (warp == 0) {
        int c = (lane < 16) ? s_ri[lane] : 0;
        #pragma unroll
        for (int o = 8; o; o >>= 1) c = max(c, __shfl_xor_sync(0xffffffffu, c, o));
        if (lane == 0) s_cmax = c;
    }
    __syncthreads();
    const float fcmax = (float)s_cmax;

    // exp(count - max); each slot owned by one thread
    float sum = 0.f;
    float* sh_f = reinterpret_cast<float*>(sh_hist);
    #pragma unroll
    for (int k = 0; k < NBINS / NTHR; k++) {
        int i = t + k * NTHR;
        float ev = exp_ref(__fsub_rn((float)sh_hist[i], fcmax));
        sh_f[i] = ev;
        sum += ev;
    }
    #pragma unroll
    for (int o = 16; o; o >>= 1) sum += __shfl_xor_sync(0xffffffffu, sum, o);
    if (lane == 0) s_ra[warp] = sum;
    __syncthreads();
    if (warp == 0) {
        float s2 = (lane < 16) ? s_ra[lane] : 0.f;
        #pragma unroll
        for (int o = 8; o; o >>= 1) s2 += __shfl_xor_sync(0xffffffffu, s2, o);
        if (lane == 0) s_sum = s2;
    }
    __syncthreads();
    const float Z = s_sum;

    // ---------------- Gate this CTA's half of x (float4) ----------------
    const int cbeg = half * (NBINS / 2);   // 8192 columns per CTA
    const float4* xb4 = reinterpret_cast<const float4*>(x   + (size_t)row * NBINS + cbeg);
    float4*       ob4 = reinterpret_cast<float4*>      (out + (size_t)row * NBINS + cbeg);
    #pragma unroll
    for (int k = 0; k < (NBINS / 2) / (NTHR * 4); k++) {
        int i = t + k * NTHR;              // float4 index within the half
        float4 xv = xb4[i];
        int base = cbeg + i * 4;
        float p0 = __fdiv_rn(sh_f[base + 0], Z);
        float p1 = __fdiv_rn(sh_f[base + 1], Z);
        float p2 = __fdiv_rn(sh_f[base + 2], Z);
        float p3 = __fdiv_rn(sh_f[base + 3], Z);
        if (p0 < 1e-10f) p0 = 0.f;
        if (p1 < 1e-10f) p1 = 0.f;
        if (p2 < 1e-10f) p2 = 0.f;
        if (p3 < 1e-10f) p3 = 0.f;
        float4 ov;
        ov.x = __fmul_rn(__fmul_rn(xv.x, p0), 128.0f);
        ov.y = __fmul_rn(__fmul_rn(xv.y, p1), 128.0f);
        ov.z = __fmul_rn(__fmul_rn(xv.z, p2), 128.0f);
        ov.w = __fmul_rn(__fmul_rn(xv.w, p3), 128.0f);
        ob4[i] = ov;
    }
}

extern "C" void kernel_launch(void* const* d_in, const int* in_sizes, int n_in,
                              void* d_out, int out_size)
{
    const float* z_mean = (const float*)d_in[0];
    const float* z_var  = (const float*)d_in[1];
    const float* x      = (const float*)d_in[2];
    const float* eps    = (const float*)d_in[3];
    float*       out    = (float*)d_out;

    cudaFuncSetAttribute(pd_kernel, cudaFuncAttributeMaxDynamicSharedMemorySize,
                         NBINS * (int)sizeof(int));
    pd_kernel<<<NCTAS, NTHR, NBINS * sizeof(int)>>>(z_mean, z_var, x, eps, out);
}